// round 2
// baseline (speedup 1.0000x reference)
#include <cuda_runtime.h>
#include <math.h>

#define BATCH 16
#define SEQ   1024
#define DIM   384
#define NH    6
#define HD    64
#define QKV_COLS (3*DIM)
#define M_TOTAL  (BATCH*SEQ)
#define SCALE_Q  0.125f          // 64^-0.5

// Scratch (device globals; no allocations allowed)
static __device__ float g_q[(size_t)BATCH*NH*SEQ*HD];     // (B,H,N,hd), pre-scaled by SCALE_Q
static __device__ float g_k[(size_t)BATCH*NH*SEQ*HD];
static __device__ float g_v[(size_t)BATCH*NH*SEQ*HD];
static __device__ float g_att[(size_t)BATCH*SEQ*DIM];     // (B,N,D) attention output

// ---------------------------------------------------------------------------
// QKV GEMM: C = x(16384x384) @ w_qkv(384x1152) + b_qkv, scattered to g_q/g_k/g_v
// 64x64 block tile, BK=16, 256 threads, 4x4 micro-tile.
// A 64-col tile always lies inside one of {q,k,v} and one head (384 and 64 | 64).
// ---------------------------------------------------------------------------
__global__ __launch_bounds__(256, 2)
void qkv_gemm_kernel(const float* __restrict__ x,
                     const float* __restrict__ w,
                     const float* __restrict__ bias)
{
    __shared__ float As[16][68];   // As[k][m]
    __shared__ float Bs[16][68];   // Bs[k][n]
    const int tid = threadIdx.x;
    const int tx = tid & 15, ty = tid >> 4;
    const int bm = blockIdx.x * 64;
    const int bn = blockIdx.y * 64;
    const int arow = tid >> 2;            // 0..63
    const int acol = (tid & 3) << 2;      // 0,4,8,12
    const int brow = tid >> 4;            // 0..15
    const int bcol = (tid & 15) << 2;     // 0..60

    float acc[4][4] = {};

    for (int kt = 0; kt < DIM; kt += 16) {
        float4 av = *reinterpret_cast<const float4*>(
            x + (size_t)(bm + arow) * DIM + kt + acol);
        As[acol+0][arow] = av.x; As[acol+1][arow] = av.y;
        As[acol+2][arow] = av.z; As[acol+3][arow] = av.w;
        float4 bv = *reinterpret_cast<const float4*>(
            w + (size_t)(kt + brow) * QKV_COLS + bn + bcol);
        Bs[brow][bcol+0] = bv.x; Bs[brow][bcol+1] = bv.y;
        Bs[brow][bcol+2] = bv.z; Bs[brow][bcol+3] = bv.w;
        __syncthreads();
        #pragma unroll
        for (int k = 0; k < 16; k++) {
            float a[4], b[4];
            #pragma unroll
            for (int i = 0; i < 4; i++) a[i] = As[k][ty*4+i];
            #pragma unroll
            for (int j = 0; j < 4; j++) b[j] = Bs[k][tx*4+j];
            #pragma unroll
            for (int i = 0; i < 4; i++)
                #pragma unroll
                for (int j = 0; j < 4; j++)
                    acc[i][j] = fmaf(a[i], b[j], acc[i][j]);
        }
        __syncthreads();
    }

    const int s = bn / DIM;               // 0:q 1:k 2:v
    const int h = (bn % DIM) / HD;
    float* dst = (s == 0) ? g_q : ((s == 1) ? g_k : g_v);
    const float sc = (s == 0) ? SCALE_Q : 1.0f;
    #pragma unroll
    for (int i = 0; i < 4; i++) {
        int m  = bm + ty*4 + i;
        int b_ = m >> 10;                 // / SEQ
        int n_ = m & (SEQ - 1);
        size_t base = (((size_t)b_ * NH + h) * SEQ + n_) * HD;
        #pragma unroll
        for (int j = 0; j < 4; j++) {
            int d = tx*4 + j;             // bn % 64 == 0, so head-dim offset
            dst[base + d] = (acc[i][j] + bias[bn + d]) * sc;
        }
    }
}

// ---------------------------------------------------------------------------
// Fused flash-attention: per (b,h) head and 64-query tile, stream K/V in
// 64-key tiles through smem with online softmax. Writes (B,N,D) to g_att.
// Smem: Qs, KPs (K then reused for P), Vs — 3 x 64x65 fp32 = 49,920 B dynamic.
// ---------------------------------------------------------------------------
__global__ __launch_bounds__(256)
void attn_kernel()
{
    extern __shared__ float sm[];
    float* Qs  = sm;                // [64][65]  row=query, col=hd
    float* KPs = sm + 64*65;        // [64][65]  K tile, then reused as P tile
    float* Vs  = sm + 2*64*65;      // [64][65]  row=key,   col=hd

    const int tid = threadIdx.x;
    const int tx = tid & 15, ty = tid >> 4;
    const int bh = blockIdx.y;      // b*NH + h
    const int qt = blockIdx.x;      // query tile

    const float* Qg = g_q + ((size_t)bh * SEQ + qt*64) * HD;
    const float* Kg = g_k + (size_t)bh * SEQ * HD;
    const float* Vg = g_v + (size_t)bh * SEQ * HD;

    // Load Q tile (already scaled by SCALE_Q)
    #pragma unroll
    for (int r = 0; r < 4; r++) {
        int idx = tid + r*256;            // float4 index 0..1023
        int row = idx >> 4;
        int c4  = (idx & 15) << 2;
        float4 v = *reinterpret_cast<const float4*>(Qg + row*HD + c4);
        Qs[row*65+c4+0]=v.x; Qs[row*65+c4+1]=v.y;
        Qs[row*65+c4+2]=v.z; Qs[row*65+c4+3]=v.w;
    }

    float mi[4], li[4], o[4][4] = {};
    #pragma unroll
    for (int i = 0; i < 4; i++) { mi[i] = -1e30f; li[i] = 0.0f; }

    for (int t = 0; t < SEQ/64; t++) {
        __syncthreads();   // prev iter's P@V done before overwriting KPs/Vs
        #pragma unroll
        for (int r = 0; r < 4; r++) {
            int idx = tid + r*256;
            int row = idx >> 4;
            int c4  = (idx & 15) << 2;
            float4 kv = *reinterpret_cast<const float4*>(Kg + (size_t)(t*64+row)*HD + c4);
            KPs[row*65+c4+0]=kv.x; KPs[row*65+c4+1]=kv.y;
            KPs[row*65+c4+2]=kv.z; KPs[row*65+c4+3]=kv.w;
            float4 vv = *reinterpret_cast<const float4*>(Vg + (size_t)(t*64+row)*HD + c4);
            Vs[row*65+c4+0]=vv.x; Vs[row*65+c4+1]=vv.y;
            Vs[row*65+c4+2]=vv.z; Vs[row*65+c4+3]=vv.w;
        }
        __syncthreads();

        // S = Q @ K^T  (4x4 per thread)
        float s[4][4] = {};
        #pragma unroll
        for (int k = 0; k < HD; k++) {
            float a[4], b[4];
            #pragma unroll
            for (int i = 0; i < 4; i++) a[i] = Qs[(ty*4+i)*65 + k];
            #pragma unroll
            for (int j = 0; j < 4; j++) b[j] = KPs[(tx*4+j)*65 + k];
            #pragma unroll
            for (int i = 0; i < 4; i++)
                #pragma unroll
                for (int j = 0; j < 4; j++)
                    s[i][j] = fmaf(a[i], b[j], s[i][j]);
        }

        // Online softmax per row; a query row spans a 16-lane shfl group.
        #pragma unroll
        for (int i = 0; i < 4; i++) {
            float rm = fmaxf(fmaxf(s[i][0], s[i][1]), fmaxf(s[i][2], s[i][3]));
            #pragma unroll
            for (int off = 8; off >= 1; off >>= 1)
                rm = fmaxf(rm, __shfl_xor_sync(0xffffffffu, rm, off));
            float mnew  = fmaxf(mi[i], rm);
            float alpha = __expf(mi[i] - mnew);
            float rs = 0.0f;
            #pragma unroll
            for (int j = 0; j < 4; j++) { s[i][j] = __expf(s[i][j] - mnew); rs += s[i][j]; }
            #pragma unroll
            for (int off = 8; off >= 1; off >>= 1)
                rs += __shfl_xor_sync(0xffffffffu, rs, off);
            li[i] = li[i] * alpha + rs;
            mi[i] = mnew;
            #pragma unroll
            for (int j = 0; j < 4; j++) o[i][j] *= alpha;
        }

        __syncthreads();   // everyone done reading K from KPs before P overwrite

        #pragma unroll
        for (int i = 0; i < 4; i++)
            #pragma unroll
            for (int j = 0; j < 4; j++)
                KPs[(ty*4+i)*65 + tx*4+j] = s[i][j];
        __syncthreads();

        // O += P @ V   (rows=query, cols=hd via tx)
        #pragma unroll
        for (int k = 0; k < 64; k++) {
            float a[4], b[4];
            #pragma unroll
            for (int i = 0; i < 4; i++) a[i] = KPs[(ty*4+i)*65 + k];
            #pragma unroll
            for (int j = 0; j < 4; j++) b[j] = Vs[k*65 + tx*4+j];
            #pragma unroll
            for (int i = 0; i < 4; i++)
                #pragma unroll
                for (int j = 0; j < 4; j++)
                    o[i][j] = fmaf(a[i], b[j], o[i][j]);
        }
    }

    // Normalize + write (B,N,D)
    const int b_ = bh / NH, h = bh % NH;
    #pragma unroll
    for (int i = 0; i < 4; i++) {
        float inv = 1.0f / li[i];
        int n = qt*64 + ty*4 + i;
        size_t base = ((size_t)b_ * SEQ + n) * DIM + h*HD;
        #pragma unroll
        for (int j = 0; j < 4; j++)
            g_att[base + tx*4 + j] = o[i][j] * inv;
    }
}

// ---------------------------------------------------------------------------
// Proj GEMM: out = g_att(16384x384) @ w_proj(384x384) + b_proj
// ---------------------------------------------------------------------------
__global__ __launch_bounds__(256, 2)
void proj_gemm_kernel(const float* __restrict__ w,
                      const float* __restrict__ bias,
                      float* __restrict__ out)
{
    __shared__ float As[16][68];
    __shared__ float Bs[16][68];
    const int tid = threadIdx.x;
    const int tx = tid & 15, ty = tid >> 4;
    const int bm = blockIdx.x * 64;
    const int bn = blockIdx.y * 64;
    const int arow = tid >> 2;
    const int acol = (tid & 3) << 2;
    const int brow = tid >> 4;
    const int bcol = (tid & 15) << 2;

    float acc[4][4] = {};

    for (int kt = 0; kt < DIM; kt += 16) {
        float4 av = *reinterpret_cast<const float4*>(
            g_att + (size_t)(bm + arow) * DIM + kt + acol);
        As[acol+0][arow] = av.x; As[acol+1][arow] = av.y;
        As[acol+2][arow] = av.z; As[acol+3][arow] = av.w;
        float4 bv = *reinterpret_cast<const float4*>(
            w + (size_t)(kt + brow) * DIM + bn + bcol);
        Bs[brow][bcol+0] = bv.x; Bs[brow][bcol+1] = bv.y;
        Bs[brow][bcol+2] = bv.z; Bs[brow][bcol+3] = bv.w;
        __syncthreads();
        #pragma unroll
        for (int k = 0; k < 16; k++) {
            float a[4], b[4];
            #pragma unroll
            for (int i = 0; i < 4; i++) a[i] = As[k][ty*4+i];
            #pragma unroll
            for (int j = 0; j < 4; j++) b[j] = Bs[k][tx*4+j];
            #pragma unroll
            for (int i = 0; i < 4; i++)
                #pragma unroll
                for (int j = 0; j < 4; j++)
                    acc[i][j] = fmaf(a[i], b[j], acc[i][j]);
        }
        __syncthreads();
    }

    #pragma unroll
    for (int i = 0; i < 4; i++) {
        int m = bm + ty*4 + i;
        #pragma unroll
        for (int j = 0; j < 4; j++) {
            int d = tx*4 + j;
            out[(size_t)m * DIM + bn + d] = acc[i][j] + bias[bn + d];
        }
    }
}

// ---------------------------------------------------------------------------

extern "C" void kernel_launch(void* const* d_in, const int* in_sizes, int n_in,
                              void* d_out, int out_size)
{
    const float* x      = (const float*)d_in[0];
    const float* w_qkv  = (const float*)d_in[1];
    const float* b_qkv  = (const float*)d_in[2];
    const float* w_proj = (const float*)d_in[3];
    const float* b_proj = (const float*)d_in[4];
    float* out = (float*)d_out;

    const int attn_smem = 3 * 64 * 65 * sizeof(float);   // 49,920 B
    static bool attr_set = false;
    if (!attr_set) {
        cudaFuncSetAttribute(attn_kernel,
                             cudaFuncAttributeMaxDynamicSharedMemorySize, attn_smem);
        attr_set = true;
    }

    dim3 g1(M_TOTAL/64, QKV_COLS/64);        // 256 x 18
    qkv_gemm_kernel<<<g1, 256>>>(x, w_qkv, b_qkv);

    dim3 g2(SEQ/64, BATCH*NH);               // 16 x 96
    attn_kernel<<<g2, 256, attn_smem>>>();

    dim3 g3(M_TOTAL/64, DIM/64);             // 256 x 6
    proj_gemm_kernel<<<g3, 256>>>(w_proj, b_proj, out);
}

// round 11
// speedup vs baseline: 1.0000x; 1.0000x over previous
#include <cuda_runtime.h>
#include <math.h>

#define BATCH 16
#define SEQ   1024
#define DIM   384
#define NH    6
#define HD    64
#define QKV_COLS (3*DIM)
#define M_TOTAL  (BATCH*SEQ)
#define SCALE_Q  0.125f          // 64^-0.5

// Scratch (device globals; no allocations allowed)
static __device__ float g_q[(size_t)BATCH*NH*SEQ*HD];     // (B,H,N,hd), pre-scaled by SCALE_Q
static __device__ float g_k[(size_t)BATCH*NH*SEQ*HD];
static __device__ float g_v[(size_t)BATCH*NH*SEQ*HD];
static __device__ float g_att[(size_t)BATCH*SEQ*DIM];     // (B,N,D) attention output

// ---------------------------------------------------------------------------
// QKV GEMM: C = x(16384x384) @ w_qkv(384x1152) + b_qkv, scattered to g_q/g_k/g_v
// 64x64 block tile, BK=16, 256 threads, 4x4 micro-tile.
// A 64-col tile always lies inside one of {q,k,v} and one head (384 and 64 | 64).
// ---------------------------------------------------------------------------
__global__ __launch_bounds__(256, 2)
void qkv_gemm_kernel(const float* __restrict__ x,
                     const float* __restrict__ w,
                     const float* __restrict__ bias)
{
    __shared__ float As[16][68];   // As[k][m]
    __shared__ float Bs[16][68];   // Bs[k][n]
    const int tid = threadIdx.x;
    const int tx = tid & 15, ty = tid >> 4;
    const int bm = blockIdx.x * 64;
    const int bn = blockIdx.y * 64;
    const int arow = tid >> 2;            // 0..63
    const int acol = (tid & 3) << 2;      // 0,4,8,12
    const int brow = tid >> 4;            // 0..15
    const int bcol = (tid & 15) << 2;     // 0..60

    float acc[4][4] = {};

    for (int kt = 0; kt < DIM; kt += 16) {
        float4 av = *reinterpret_cast<const float4*>(
            x + (size_t)(bm + arow) * DIM + kt + acol);
        As[acol+0][arow] = av.x; As[acol+1][arow] = av.y;
        As[acol+2][arow] = av.z; As[acol+3][arow] = av.w;
        float4 bv = *reinterpret_cast<const float4*>(
            w + (size_t)(kt + brow) * QKV_COLS + bn + bcol);
        Bs[brow][bcol+0] = bv.x; Bs[brow][bcol+1] = bv.y;
        Bs[brow][bcol+2] = bv.z; Bs[brow][bcol+3] = bv.w;
        __syncthreads();
        #pragma unroll
        for (int k = 0; k < 16; k++) {
            float a[4], b[4];
            #pragma unroll
            for (int i = 0; i < 4; i++) a[i] = As[k][ty*4+i];
            #pragma unroll
            for (int j = 0; j < 4; j++) b[j] = Bs[k][tx*4+j];
            #pragma unroll
            for (int i = 0; i < 4; i++)
                #pragma unroll
                for (int j = 0; j < 4; j++)
                    acc[i][j] = fmaf(a[i], b[j], acc[i][j]);
        }
        __syncthreads();
    }

    const int s = bn / DIM;               // 0:q 1:k 2:v
    const int h = (bn % DIM) / HD;
    float* dst = (s == 0) ? g_q : ((s == 1) ? g_k : g_v);
    const float sc = (s == 0) ? SCALE_Q : 1.0f;
    #pragma unroll
    for (int i = 0; i < 4; i++) {
        int m  = bm + ty*4 + i;
        int b_ = m >> 10;                 // / SEQ
        int n_ = m & (SEQ - 1);
        size_t base = (((size_t)b_ * NH + h) * SEQ + n_) * HD;
        #pragma unroll
        for (int j = 0; j < 4; j++) {
            int d = tx*4 + j;             // bn % 64 == 0, so head-dim offset
            dst[base + d] = (acc[i][j] + bias[bn + d]) * sc;
        }
    }
}

// ---------------------------------------------------------------------------
// Fused flash-attention: per (b,h) head and 64-query tile, stream K/V in
// 64-key tiles through smem with online softmax. Writes (B,N,D) to g_att.
// Smem: Qs, KPs (K then reused for P), Vs — 3 x 64x65 fp32 = 49,920 B dynamic.
// ---------------------------------------------------------------------------
__global__ __launch_bounds__(256)
void attn_kernel()
{
    extern __shared__ float sm[];
    float* Qs  = sm;                // [64][65]  row=query, col=hd
    float* KPs = sm + 64*65;        // [64][65]  K tile, then reused as P tile
    float* Vs  = sm + 2*64*65;      // [64][65]  row=key,   col=hd

    const int tid = threadIdx.x;
    const int tx = tid & 15, ty = tid >> 4;
    const int bh = blockIdx.y;      // b*NH + h
    const int qt = blockIdx.x;      // query tile

    const float* Qg = g_q + ((size_t)bh * SEQ + qt*64) * HD;
    const float* Kg = g_k + (size_t)bh * SEQ * HD;
    const float* Vg = g_v + (size_t)bh * SEQ * HD;

    // Load Q tile (already scaled by SCALE_Q)
    #pragma unroll
    for (int r = 0; r < 4; r++) {
        int idx = tid + r*256;            // float4 index 0..1023
        int row = idx >> 4;
        int c4  = (idx & 15) << 2;
        float4 v = *reinterpret_cast<const float4*>(Qg + row*HD + c4);
        Qs[row*65+c4+0]=v.x; Qs[row*65+c4+1]=v.y;
        Qs[row*65+c4+2]=v.z; Qs[row*65+c4+3]=v.w;
    }

    float mi[4], li[4], o[4][4] = {};
    #pragma unroll
    for (int i = 0; i < 4; i++) { mi[i] = -1e30f; li[i] = 0.0f; }

    for (int t = 0; t < SEQ/64; t++) {
        __syncthreads();   // prev iter's P@V done before overwriting KPs/Vs
        #pragma unroll
        for (int r = 0; r < 4; r++) {
            int idx = tid + r*256;
            int row = idx >> 4;
            int c4  = (idx & 15) << 2;
            float4 kv = *reinterpret_cast<const float4*>(Kg + (size_t)(t*64+row)*HD + c4);
            KPs[row*65+c4+0]=kv.x; KPs[row*65+c4+1]=kv.y;
            KPs[row*65+c4+2]=kv.z; KPs[row*65+c4+3]=kv.w;
            float4 vv = *reinterpret_cast<const float4*>(Vg + (size_t)(t*64+row)*HD + c4);
            Vs[row*65+c4+0]=vv.x; Vs[row*65+c4+1]=vv.y;
            Vs[row*65+c4+2]=vv.z; Vs[row*65+c4+3]=vv.w;
        }
        __syncthreads();

        // S = Q @ K^T  (4x4 per thread)
        float s[4][4] = {};
        #pragma unroll
        for (int k = 0; k < HD; k++) {
            float a[4], b[4];
            #pragma unroll
            for (int i = 0; i < 4; i++) a[i] = Qs[(ty*4+i)*65 + k];
            #pragma unroll
            for (int j = 0; j < 4; j++) b[j] = KPs[(tx*4+j)*65 + k];
            #pragma unroll
            for (int i = 0; i < 4; i++)
                #pragma unroll
                for (int j = 0; j < 4; j++)
                    s[i][j] = fmaf(a[i], b[j], s[i][j]);
        }

        // Online softmax per row; a query row spans a 16-lane shfl group.
        #pragma unroll
        for (int i = 0; i < 4; i++) {
            float rm = fmaxf(fmaxf(s[i][0], s[i][1]), fmaxf(s[i][2], s[i][3]));
            #pragma unroll
            for (int off = 8; off >= 1; off >>= 1)
                rm = fmaxf(rm, __shfl_xor_sync(0xffffffffu, rm, off));
            float mnew  = fmaxf(mi[i], rm);
            float alpha = __expf(mi[i] - mnew);
            float rs = 0.0f;
            #pragma unroll
            for (int j = 0; j < 4; j++) { s[i][j] = __expf(s[i][j] - mnew); rs += s[i][j]; }
            #pragma unroll
            for (int off = 8; off >= 1; off >>= 1)
                rs += __shfl_xor_sync(0xffffffffu, rs, off);
            li[i] = li[i] * alpha + rs;
            mi[i] = mnew;
            #pragma unroll
            for (int j = 0; j < 4; j++) o[i][j] *= alpha;
        }

        __syncthreads();   // everyone done reading K from KPs before P overwrite

        #pragma unroll
        for (int i = 0; i < 4; i++)
            #pragma unroll
            for (int j = 0; j < 4; j++)
                KPs[(ty*4+i)*65 + tx*4+j] = s[i][j];
        __syncthreads();

        // O += P @ V   (rows=query, cols=hd via tx)
        #pragma unroll
        for (int k = 0; k < 64; k++) {
            float a[4], b[4];
            #pragma unroll
            for (int i = 0; i < 4; i++) a[i] = KPs[(ty*4+i)*65 + k];
            #pragma unroll
            for (int j = 0; j < 4; j++) b[j] = Vs[k*65 + tx*4+j];
            #pragma unroll
            for (int i = 0; i < 4; i++)
                #pragma unroll
                for (int j = 0; j < 4; j++)
                    o[i][j] = fmaf(a[i], b[j], o[i][j]);
        }
    }

    // Normalize + write (B,N,D)
    const int b_ = bh / NH, h = bh % NH;
    #pragma unroll
    for (int i = 0; i < 4; i++) {
        float inv = 1.0f / li[i];
        int n = qt*64 + ty*4 + i;
        size_t base = ((size_t)b_ * SEQ + n) * DIM + h*HD;
        #pragma unroll
        for (int j = 0; j < 4; j++)
            g_att[base + tx*4 + j] = o[i][j] * inv;
    }
}

// ---------------------------------------------------------------------------
// Proj GEMM: out = g_att(16384x384) @ w_proj(384x384) + b_proj
// ---------------------------------------------------------------------------
__global__ __launch_bounds__(256, 2)
void proj_gemm_kernel(const float* __restrict__ w,
                      const float* __restrict__ bias,
                      float* __restrict__ out)
{
    __shared__ float As[16][68];
    __shared__ float Bs[16][68];
    const int tid = threadIdx.x;
    const int tx = tid & 15, ty = tid >> 4;
    const int bm = blockIdx.x * 64;
    const int bn = blockIdx.y * 64;
    const int arow = tid >> 2;
    const int acol = (tid & 3) << 2;
    const int brow = tid >> 4;
    const int bcol = (tid & 15) << 2;

    float acc[4][4] = {};

    for (int kt = 0; kt < DIM; kt += 16) {
        float4 av = *reinterpret_cast<const float4*>(
            g_att + (size_t)(bm + arow) * DIM + kt + acol);
        As[acol+0][arow] = av.x; As[acol+1][arow] = av.y;
        As[acol+2][arow] = av.z; As[acol+3][arow] = av.w;
        float4 bv = *reinterpret_cast<const float4*>(
            w + (size_t)(kt + brow) * DIM + bn + bcol);
        Bs[brow][bcol+0] = bv.x; Bs[brow][bcol+1] = bv.y;
        Bs[brow][bcol+2] = bv.z; Bs[brow][bcol+3] = bv.w;
        __syncthreads();
        #pragma unroll
        for (int k = 0; k < 16; k++) {
            float a[4], b[4];
            #pragma unroll
            for (int i = 0; i < 4; i++) a[i] = As[k][ty*4+i];
            #pragma unroll
            for (int j = 0; j < 4; j++) b[j] = Bs[k][tx*4+j];
            #pragma unroll
            for (int i = 0; i < 4; i++)
                #pragma unroll
                for (int j = 0; j < 4; j++)
                    acc[i][j] = fmaf(a[i], b[j], acc[i][j]);
        }
        __syncthreads();
    }

    #pragma unroll
    for (int i = 0; i < 4; i++) {
        int m = bm + ty*4 + i;
        #pragma unroll
        for (int j = 0; j < 4; j++) {
            int d = tx*4 + j;
            out[(size_t)m * DIM + bn + d] = acc[i][j] + bias[bn + d];
        }
    }
}

// ---------------------------------------------------------------------------

extern "C" void kernel_launch(void* const* d_in, const int* in_sizes, int n_in,
                              void* d_out, int out_size)
{
    const float* x      = (const float*)d_in[0];
    const float* w_qkv  = (const float*)d_in[1];
    const float* b_qkv  = (const float*)d_in[2];
    const float* w_proj = (const float*)d_in[3];
    const float* b_proj = (const float*)d_in[4];
    float* out = (float*)d_out;

    const int attn_smem = 3 * 64 * 65 * sizeof(float);   // 49,920 B
    static bool attr_set = false;
    if (!attr_set) {
        cudaFuncSetAttribute(attn_kernel,
                             cudaFuncAttributeMaxDynamicSharedMemorySize, attn_smem);
        attr_set = true;
    }

    dim3 g1(M_TOTAL/64, QKV_COLS/64);        // 256 x 18
    qkv_gemm_kernel<<<g1, 256>>>(x, w_qkv, b_qkv);

    dim3 g2(SEQ/64, BATCH*NH);               // 16 x 96
    attn_kernel<<<g2, 256, attn_smem>>>();

    dim3 g3(M_TOTAL/64, DIM/64);             // 256 x 6
    proj_gemm_kernel<<<g3, 256>>>(w_proj, b_proj, out);
}